// round 1
// baseline (speedup 1.0000x reference)
#include <cuda_runtime.h>
#include <math.h>

#define N_PTS   131072
#define WIDTH   256
#define P       16          // points per CTA
#define THREADS 512         // one warp per point
#define KT      32          // K tile for W streaming
#define LDA     97          // As row stride (96 rows + 1 pad)

#define SMEM_A_FLOATS (WIDTH * LDA)        // 24832
#define SMEM_B_FLOATS (2 * KT * WIDTH)     // 16384
#define SMEM_BYTES   ((SMEM_A_FLOATS + SMEM_B_FLOATS) * 4)  // 164864

__device__ __forceinline__ float fast_tanh(float x) {
    // tanh(x) = 1 - 2/(exp(2x)+1); exact limits at +-inf, ~1e-7 abs error
    float e = __expf(2.0f * x);
    return 1.0f - __fdividef(2.0f, e + 1.0f);
}

__global__ void __launch_bounds__(THREADS, 1)
pde_kernel(const float* __restrict__ xyt,
           const float* __restrict__ w0, const float* __restrict__ b0,
           const float* __restrict__ w1, const float* __restrict__ b1,
           const float* __restrict__ w2, const float* __restrict__ b2,
           const float* __restrict__ w3, const float* __restrict__ b3,
           const float* __restrict__ w4, const float* __restrict__ b4,
           const float* __restrict__ w5, const float* __restrict__ b5,
           const float* __restrict__ w6, const float* __restrict__ b6,
           float* __restrict__ out)
{
    extern __shared__ float smem[];
    float* As = smem;                      // [WIDTH][LDA] : As[k][6*p + c]
    float* Bs = smem + SMEM_A_FLOATS;      // [2][KT][WIDTH]

    const int t  = threadIdx.x;
    const int p  = t >> 5;                 // local point = warp id
    const int g  = t & 31;                 // lane
    const int pg = blockIdx.x * P + p;     // global point

    const float x  = xyt[3 * pg + 0];
    const float y  = xyt[3 * pg + 1];
    const float tt = xyt[3 * pg + 2];

    float* Ap = As + 6 * p;                // row base for this point

    // ---------------- Layer 0: 3 -> 256 + tanh (seeds all 6 channels) -----
    #pragma unroll
    for (int m = 0; m < 4; m++) {
        #pragma unroll
        for (int e = 0; e < 2; e++) {
            int j = 2 * g + 64 * m + e;
            float wx = w0[j];
            float wy = w0[WIDTH + j];
            float wt = w0[2 * WIDTH + j];
            float z  = fmaf(x, wx, fmaf(y, wy, fmaf(tt, wt, b0[j])));
            float v  = fast_tanh(z);
            float s  = 1.0f - v * v;
            float* r = Ap + j * LDA;
            r[0] = v;
            r[1] = s * wx;                      // v_x
            r[2] = s * wy;                      // v_y
            r[3] = s * wt;                      // v_t
            r[4] = -2.0f * v * s * wx * wx;     // v_xx (z_xx = 0)
            r[5] = -2.0f * v * s * wy * wy;     // v_yy
        }
    }
    __syncthreads();

    const float* Ws[5]  = { w1, w2, w3, w4, w5 };
    const float* Bbs[5] = { b1, b2, b3, b4, b5 };

    // ---------------- Layers 1..5: [96 x 256] @ [256 x 256] + tanh rules ---
    for (int l = 0; l < 5; l++) {
        const float* W = Ws[l];

        float acc[6][8];
        #pragma unroll
        for (int c = 0; c < 6; c++)
            #pragma unroll
            for (int mm = 0; mm < 8; mm++) acc[c][mm] = 0.0f;

        // prefetch tile 0 into registers
        float4 rb[4];
        {
            const float4* Wv = (const float4*)W;
            #pragma unroll
            for (int i = 0; i < 4; i++) rb[i] = Wv[t + THREADS * i];
        }

        int buf = 0;
        for (int kt = 0; kt < WIDTH / KT; kt++) {
            // stage current tile into smem
            float4* bsv = (float4*)(Bs + buf * KT * WIDTH);
            #pragma unroll
            for (int i = 0; i < 4; i++) bsv[t + THREADS * i] = rb[i];
            __syncthreads();

            // prefetch next tile (latency hidden under compute)
            if (kt < WIDTH / KT - 1) {
                const float4* Wn = (const float4*)(W + (kt + 1) * KT * WIDTH);
                #pragma unroll
                for (int i = 0; i < 4; i++) rb[i] = Wn[t + THREADS * i];
            }

            const float* Brow = Bs + buf * KT * WIDTH + 2 * g;
            const float* Ak   = As + (kt * KT) * LDA + 6 * p;

            #pragma unroll 4
            for (int k = 0; k < KT; k++) {
                float a[6];
                #pragma unroll
                for (int c = 0; c < 6; c++) a[c] = Ak[c];   // warp-uniform broadcast
                Ak += LDA;
                const float* br = Brow + k * WIDTH;
                #pragma unroll
                for (int m = 0; m < 4; m++) {
                    float2 bv = *(const float2*)(br + 64 * m);
                    #pragma unroll
                    for (int c = 0; c < 6; c++) {
                        acc[c][2 * m]     = fmaf(a[c], bv.x, acc[c][2 * m]);
                        acc[c][2 * m + 1] = fmaf(a[c], bv.y, acc[c][2 * m + 1]);
                    }
                }
            }
            buf ^= 1;
        }
        __syncthreads();   // all warps done READING As before overwrite

        const float* bias = Bbs[l];
        #pragma unroll
        for (int m = 0; m < 4; m++) {
            #pragma unroll
            for (int e = 0; e < 2; e++) {
                int mm = 2 * m + e;
                int j  = 2 * g + 64 * m + e;
                float u   = acc[0][mm] + bias[j];
                float ux  = acc[1][mm];
                float uy  = acc[2][mm];
                float ut  = acc[3][mm];
                float uxx = acc[4][mm];
                float uyy = acc[5][mm];
                float v = fast_tanh(u);
                float s = 1.0f - v * v;
                float tvs = 2.0f * v * s;
                float* r = Ap + j * LDA;
                r[0] = v;
                r[1] = s * ux;
                r[2] = s * uy;
                r[3] = s * ut;
                r[4] = fmaf(s, uxx, -tvs * ux * ux);
                r[5] = fmaf(s, uyy, -tvs * uy * uy);
            }
        }
        __syncthreads();   // As visible for next layer
    }

    // ---------------- Layer 6: 256 -> 1 (linear), warp reduction -----------
    float h = 0.f, hx = 0.f, hy = 0.f, ht = 0.f, hxx = 0.f, hyy = 0.f;
    #pragma unroll
    for (int m = 0; m < 4; m++) {
        #pragma unroll
        for (int e = 0; e < 2; e++) {
            int j = 2 * g + 64 * m + e;
            float wv = w6[j];
            const float* r = Ap + j * LDA;
            h   = fmaf(r[0], wv, h);
            hx  = fmaf(r[1], wv, hx);
            hy  = fmaf(r[2], wv, hy);
            ht  = fmaf(r[3], wv, ht);
            hxx = fmaf(r[4], wv, hxx);
            hyy = fmaf(r[5], wv, hyy);
        }
    }
    #pragma unroll
    for (int off = 16; off > 0; off >>= 1) {
        h   += __shfl_xor_sync(0xFFFFFFFFu, h,   off);
        hx  += __shfl_xor_sync(0xFFFFFFFFu, hx,  off);
        hy  += __shfl_xor_sync(0xFFFFFFFFu, hy,  off);
        ht  += __shfl_xor_sync(0xFFFFFFFFu, ht,  off);
        hxx += __shfl_xor_sync(0xFFFFFFFFu, hxx, off);
        hyy += __shfl_xor_sync(0xFFFFFFFFu, hyy, off);
    }

    if (g == 0) {
        h += b6[0];
        const float PI = 3.14159265358979323846f;
        float f = sinf(PI * x) * sinf(PI * y) * expf(-tt);
        // res = MU*ht - K*(h*(hxx+hyy) + hx^2 + hy^2) - f ;  MU=1, K=0.5
        float res = ht - 0.5f * (h * (hxx + hyy) + hx * hx + hy * hy) - f;
        out[pg] = res;
    }
}

extern "C" void kernel_launch(void* const* d_in, const int* in_sizes, int n_in,
                              void* d_out, int out_size)
{
    const float* xyt = (const float*)d_in[0];
    const float* w0  = (const float*)d_in[1];
    const float* b0  = (const float*)d_in[2];
    const float* w1  = (const float*)d_in[3];
    const float* b1  = (const float*)d_in[4];
    const float* w2  = (const float*)d_in[5];
    const float* b2  = (const float*)d_in[6];
    const float* w3  = (const float*)d_in[7];
    const float* b3  = (const float*)d_in[8];
    const float* w4  = (const float*)d_in[9];
    const float* b4  = (const float*)d_in[10];
    const float* w5  = (const float*)d_in[11];
    const float* b5  = (const float*)d_in[12];
    const float* w6  = (const float*)d_in[13];
    const float* b6  = (const float*)d_in[14];

    cudaFuncSetAttribute(pde_kernel,
                         cudaFuncAttributeMaxDynamicSharedMemorySize,
                         SMEM_BYTES);

    dim3 grid(N_PTS / P);
    pde_kernel<<<grid, THREADS, SMEM_BYTES>>>(
        xyt, w0, b0, w1, b1, w2, b2, w3, b3, w4, b4, w5, b5, w6, b6,
        (float*)d_out);
}

// round 2
// speedup vs baseline: 1.0661x; 1.0661x over previous
#include <cuda_runtime.h>
#include <math.h>

#define N_PTS   131072
#define WIDTH   256
#define P       16          // points per CTA
#define THREADS 512         // one warp per point
#define KT      32          // K tile for W streaming
#define LDA     97          // As row stride (96 rows + 1 pad)

#define SMEM_A_FLOATS (WIDTH * LDA)        // 24832
#define SMEM_B_FLOATS (2 * KT * WIDTH)     // 16384
#define SMEM_BYTES   ((SMEM_A_FLOATS + SMEM_B_FLOATS) * 4)  // 164864

typedef unsigned long long u64;

__device__ __forceinline__ float fast_tanh(float x) {
    float e = __expf(2.0f * x);
    return 1.0f - __fdividef(2.0f, e + 1.0f);
}

// pack one float into both lanes of an f32x2
__device__ __forceinline__ u64 pack2(float a) {
    u64 r;
    asm("mov.b64 %0, {%1, %1};" : "=l"(r) : "f"(a));
    return r;
}
// packed dual FMA: acc.{lo,hi} += a.{lo,hi} * b.{lo,hi}
__device__ __forceinline__ void ffma2(u64& acc, u64 a, u64 b) {
    asm("fma.rn.f32x2 %0, %1, %2, %0;" : "+l"(acc) : "l"(a), "l"(b));
}
__device__ __forceinline__ float2 unpack2(u64 v) {
    float2 f;
    asm("mov.b64 {%0, %1}, %2;" : "=f"(f.x), "=f"(f.y) : "l"(v));
    return f;
}

__global__ void __launch_bounds__(THREADS, 1)
pde_kernel(const float* __restrict__ xyt,
           const float* __restrict__ w0, const float* __restrict__ b0,
           const float* __restrict__ w1, const float* __restrict__ b1,
           const float* __restrict__ w2, const float* __restrict__ b2,
           const float* __restrict__ w3, const float* __restrict__ b3,
           const float* __restrict__ w4, const float* __restrict__ b4,
           const float* __restrict__ w5, const float* __restrict__ b5,
           const float* __restrict__ w6, const float* __restrict__ b6,
           float* __restrict__ out)
{
    extern __shared__ float smem[];
    float* As = smem;                      // [WIDTH][LDA] : As[k][6*p + c]
    float* Bs = smem + SMEM_A_FLOATS;      // [2][KT][WIDTH]

    const int t  = threadIdx.x;
    const int p  = t >> 5;                 // local point = warp id
    const int g  = t & 31;                 // lane
    const int pg = blockIdx.x * P + p;     // global point

    const float x  = xyt[3 * pg + 0];
    const float y  = xyt[3 * pg + 1];
    const float tt = xyt[3 * pg + 2];

    float* Ap = As + 6 * p;                // row base for this point

    // ---------------- Layer 0: 3 -> 256 + tanh (seeds all 6 channels) -----
    #pragma unroll
    for (int m = 0; m < 4; m++) {
        #pragma unroll
        for (int e = 0; e < 2; e++) {
            int j = 2 * g + 64 * m + e;
            float wx = w0[j];
            float wy = w0[WIDTH + j];
            float wt = w0[2 * WIDTH + j];
            float z  = fmaf(x, wx, fmaf(y, wy, fmaf(tt, wt, b0[j])));
            float v  = fast_tanh(z);
            float s  = 1.0f - v * v;
            float* r = Ap + j * LDA;
            r[0] = v;
            r[1] = s * wx;                      // v_x
            r[2] = s * wy;                      // v_y
            r[3] = s * wt;                      // v_t
            r[4] = -2.0f * v * s * wx * wx;     // v_xx (z_xx = 0)
            r[5] = -2.0f * v * s * wy * wy;     // v_yy
        }
    }
    __syncthreads();

    const float* Ws[5]  = { w1, w2, w3, w4, w5 };
    const float* Bbs[5] = { b1, b2, b3, b4, b5 };

    // ---------------- Layers 1..5: [96 x 256] @ [256 x 256] + tanh rules ---
    for (int l = 0; l < 5; l++) {
        const float* W = Ws[l];

        // acc2[c][m] packs outputs (2g+64m, 2g+64m+1) for channel c
        u64 acc2[6][4];
        #pragma unroll
        for (int c = 0; c < 6; c++)
            #pragma unroll
            for (int m = 0; m < 4; m++) acc2[c][m] = 0ull;

        // prefetch tile 0 into registers
        float4 rb[4];
        {
            const float4* Wv = (const float4*)W;
            #pragma unroll
            for (int i = 0; i < 4; i++) rb[i] = Wv[t + THREADS * i];
        }

        int buf = 0;
        for (int kt = 0; kt < WIDTH / KT; kt++) {
            // stage current tile into smem
            float4* bsv = (float4*)(Bs + buf * KT * WIDTH);
            #pragma unroll
            for (int i = 0; i < 4; i++) bsv[t + THREADS * i] = rb[i];
            __syncthreads();

            // prefetch next tile (latency hidden under compute)
            if (kt < WIDTH / KT - 1) {
                const float4* Wn = (const float4*)(W + (kt + 1) * KT * WIDTH);
                #pragma unroll
                for (int i = 0; i < 4; i++) rb[i] = Wn[t + THREADS * i];
            }

            const float* Brow = Bs + buf * KT * WIDTH + 2 * g;
            const float* Ak   = As + (kt * KT) * LDA + 6 * p;

            #pragma unroll 4
            for (int k = 0; k < KT; k++) {
                u64 ad[6];
                #pragma unroll
                for (int c = 0; c < 6; c++) ad[c] = pack2(Ak[c]);  // broadcast + dup
                Ak += LDA;
                const float* br = Brow + k * WIDTH;
                #pragma unroll
                for (int m = 0; m < 4; m++) {
                    u64 bv = *(const u64*)(br + 64 * m);   // {b_j, b_j+1}, 8B aligned
                    #pragma unroll
                    for (int c = 0; c < 6; c++)
                        ffma2(acc2[c][m], ad[c], bv);
                }
            }
            buf ^= 1;
        }
        __syncthreads();   // all warps done READING As before overwrite

        const float* bias = Bbs[l];
        #pragma unroll
        for (int m = 0; m < 4; m++) {
            float2 au   = unpack2(acc2[0][m]);
            float2 aux  = unpack2(acc2[1][m]);
            float2 auy  = unpack2(acc2[2][m]);
            float2 aut  = unpack2(acc2[3][m]);
            float2 auxx = unpack2(acc2[4][m]);
            float2 auyy = unpack2(acc2[5][m]);
            #pragma unroll
            for (int e = 0; e < 2; e++) {
                int j = 2 * g + 64 * m + e;
                float u   = (e ? au.y   : au.x) + bias[j];
                float ux  = (e ? aux.y  : aux.x);
                float uy  = (e ? auy.y  : auy.x);
                float ut  = (e ? aut.y  : aut.x);
                float uxx = (e ? auxx.y : auxx.x);
                float uyy = (e ? auyy.y : auyy.x);
                float v = fast_tanh(u);
                float s = 1.0f - v * v;
                float tvs = 2.0f * v * s;
                float* r = Ap + j * LDA;
                r[0] = v;
                r[1] = s * ux;
                r[2] = s * uy;
                r[3] = s * ut;
                r[4] = fmaf(s, uxx, -tvs * ux * ux);
                r[5] = fmaf(s, uyy, -tvs * uy * uy);
            }
        }
        __syncthreads();   // As visible for next layer
    }

    // ---------------- Layer 6: 256 -> 1 (linear), warp reduction -----------
    float h = 0.f, hx = 0.f, hy = 0.f, ht = 0.f, hxx = 0.f, hyy = 0.f;
    #pragma unroll
    for (int m = 0; m < 4; m++) {
        #pragma unroll
        for (int e = 0; e < 2; e++) {
            int j = 2 * g + 64 * m + e;
            float wv = w6[j];
            const float* r = Ap + j * LDA;
            h   = fmaf(r[0], wv, h);
            hx  = fmaf(r[1], wv, hx);
            hy  = fmaf(r[2], wv, hy);
            ht  = fmaf(r[3], wv, ht);
            hxx = fmaf(r[4], wv, hxx);
            hyy = fmaf(r[5], wv, hyy);
        }
    }
    #pragma unroll
    for (int off = 16; off > 0; off >>= 1) {
        h   += __shfl_xor_sync(0xFFFFFFFFu, h,   off);
        hx  += __shfl_xor_sync(0xFFFFFFFFu, hx,  off);
        hy  += __shfl_xor_sync(0xFFFFFFFFu, hy,  off);
        ht  += __shfl_xor_sync(0xFFFFFFFFu, ht,  off);
        hxx += __shfl_xor_sync(0xFFFFFFFFu, hxx, off);
        hyy += __shfl_xor_sync(0xFFFFFFFFu, hyy, off);
    }

    if (g == 0) {
        h += b6[0];
        const float PI = 3.14159265358979323846f;
        float f = sinf(PI * x) * sinf(PI * y) * expf(-tt);
        // res = MU*ht - K*(h*(hxx+hyy) + hx^2 + hy^2) - f ;  MU=1, K=0.5
        float res = ht - 0.5f * (h * (hxx + hyy) + hx * hx + hy * hy) - f;
        out[pg] = res;
    }
}

extern "C" void kernel_launch(void* const* d_in, const int* in_sizes, int n_in,
                              void* d_out, int out_size)
{
    const float* xyt = (const float*)d_in[0];
    const float* w0  = (const float*)d_in[1];
    const float* b0  = (const float*)d_in[2];
    const float* w1  = (const float*)d_in[3];
    const float* b1  = (const float*)d_in[4];
    const float* w2  = (const float*)d_in[5];
    const float* b2  = (const float*)d_in[6];
    const float* w3  = (const float*)d_in[7];
    const float* b3  = (const float*)d_in[8];
    const float* w4  = (const float*)d_in[9];
    const float* b4  = (const float*)d_in[10];
    const float* w5  = (const float*)d_in[11];
    const float* b5  = (const float*)d_in[12];
    const float* w6  = (const float*)d_in[13];
    const float* b6  = (const float*)d_in[14];

    cudaFuncSetAttribute(pde_kernel,
                         cudaFuncAttributeMaxDynamicSharedMemorySize,
                         SMEM_BYTES);

    dim3 grid(N_PTS / P);
    pde_kernel<<<grid, THREADS, SMEM_BYTES>>>(
        xyt, w0, b0, w1, b1, w2, b2, w3, b3, w4, b4, w5, b5, w6, b6,
        (float*)d_out);
}